// round 7
// baseline (speedup 1.0000x reference)
#include <cuda_runtime.h>
#include <cuda_bf16.h>
#include <cstdint>

#define SEQ 8192
#define HD  128

__device__ __align__(256) __nv_bfloat16 g_Qh[SEQ * HD];
__device__ __align__(256) __nv_bfloat16 g_Ql[SEQ * HD];
__device__ __align__(256) __nv_bfloat16 g_Kh[SEQ * HD];
__device__ __align__(256) __nv_bfloat16 g_Kl[SEQ * HD];
__device__ __align__(256) __nv_bfloat16 g_Vth[HD * SEQ];   // V'^T hi: [d][m]
__device__ __align__(256) __nv_bfloat16 g_Vtl[HD * SEQ];   // V'^T lo
__device__ __align__(256) __nv_bfloat16 g_Eh[(size_t)SEQ * SEQ];  // E^T hi: [k][q]
__device__ __align__(256) __nv_bfloat16 g_El[(size_t)SEQ * SEQ];  // E^T lo
__device__ __align__(8) float g_psum[2][SEQ];
__device__ __align__(16) float g_part[2][SEQ * HD];

#define ESHIFT 60.0f

__device__ __forceinline__ uint32_t smem_u32(const void* p) {
    uint32_t a;
    asm("{ .reg .u64 t; cvta.to.shared.u64 t, %1; cvt.u32.u64 %0, t; }" : "=r"(a) : "l"(p));
    return a;
}
#define CP16(dst, src) asm volatile("cp.async.cg.shared.global [%0], [%1], 16;" :: "r"(dst), "l"(src))
#define CP_COMMIT()    asm volatile("cp.async.commit_group;" ::: "memory")
#define CP_WAIT0()     asm volatile("cp.async.wait_group 0;" ::: "memory")
#define CP_WAIT1()     asm volatile("cp.async.wait_group 1;" ::: "memory")

#define LDSM4(r, addr) \
    asm volatile("ldmatrix.sync.aligned.m8n8.x4.shared.b16 {%0,%1,%2,%3}, [%4];" \
        : "=r"((r)[0]), "=r"((r)[1]), "=r"((r)[2]), "=r"((r)[3]) : "r"(addr))
#define LDSM4T(r, addr) \
    asm volatile("ldmatrix.sync.aligned.m8n8.x4.trans.shared.b16 {%0,%1,%2,%3}, [%4];" \
        : "=r"((r)[0]), "=r"((r)[1]), "=r"((r)[2]), "=r"((r)[3]) : "r"(addr))

#define MMA(c, a, b0, b1) \
    asm volatile("mma.sync.aligned.m16n8k16.row.col.f32.bf16.bf16.f32 " \
        "{%0,%1,%2,%3},{%4,%5,%6,%7},{%8,%9},{%0,%1,%2,%3};" \
        : "+f"((c)[0]), "+f"((c)[1]), "+f"((c)[2]), "+f"((c)[3]) \
        : "r"((a)[0]), "r"((a)[1]), "r"((a)[2]), "r"((a)[3]), "r"(b0), "r"(b1))

#define ST128 272u   // 128-col bf16 tile row stride (256B + 16 pad)
#define ST64  144u   // 64-col bf16 tile row stride (128B + 16 pad)
#define ST32  80u    // 32-col bf16 tile row stride (64B + 16 pad)

__device__ __forceinline__ void cp128(uint32_t dst, const __nv_bfloat16* g, int rows, int tid) {
    for (int i = tid; i < rows * 16; i += 256) {
        int r = i >> 4, c = i & 15;
        CP16(dst + (uint32_t)r * ST128 + (uint32_t)c * 16, g + r * HD + c * 8);
    }
}

// ============================ converts ======================================
__global__ void conv_qk_kernel(const float* __restrict__ Q, const float* __restrict__ K) {
    int i = blockIdx.x * blockDim.x + threadIdx.x;
    if (i >= SEQ * HD) return;
    float q = Q[i];
    __nv_bfloat16 qh = __float2bfloat16_rn(q);
    g_Qh[i] = qh; g_Ql[i] = __float2bfloat16_rn(q - __bfloat162float(qh));
    float k = K[i];
    __nv_bfloat16 kh = __float2bfloat16_rn(k);
    g_Kh[i] = kh; g_Kl[i] = __float2bfloat16_rn(k - __bfloat162float(kh));
}

// V'[m,:] = V[m,:] / colsumE[m], transposed + split hi/lo
__global__ void scale_v_kernel(const float* __restrict__ V) {
    __shared__ float sv[64 * HD];
    __shared__ float sinv[64];
    int m0 = blockIdx.x * 64;
    for (int i = threadIdx.x; i < 64 * HD; i += 128) sv[i] = V[m0 * HD + i];
    if (threadIdx.x < 64) {
        int m = m0 + threadIdx.x;
        sinv[threadIdx.x] = 1.0f / (g_psum[0][m] + g_psum[1][m]);
    }
    __syncthreads();
    for (int i = threadIdx.x; i < 64 * HD; i += 128) {
        int d = i >> 6, j = i & 63;
        float v = sv[j * HD + d] * sinv[j];
        __nv_bfloat16 h = __float2bfloat16_rn(v);
        g_Vth[d * SEQ + m0 + j] = h;
        g_Vtl[d * SEQ + m0 + j] = __float2bfloat16_rn(v - __bfloat162float(h));
    }
}

// ============================ pass A ========================================
// grid(64,2): 128 keys x 4096 queries. A = K rows (persistent frags), stream
// 32-query chunks. E = exp(S-60) -> split hi/lo -> staged -> gmem E^T; colsums.
#define PA_K      0u
#define PA_K_LO   34816u                  // 128*272
#define PA_Q      69632u
#define PA_QSTG   17408u                  // 32*272*2 (hi+lo) per stage
#define PA_Q_LO   8704u
#define PA_E      104448u                 // staging: hi [128][ST32], lo +10240
#define PA_E_LO   10240u
#define PA_SMEM   (104448 + 20480)        // 124928

__global__ __launch_bounds__(256, 1)
void passA_kernel() {
    extern __shared__ char sm[];
    const uint32_t s0 = smem_u32(sm);
    const int tid = threadIdx.x, wid = tid >> 5, lane = tid & 31;
    const int m0 = blockIdx.x * 128, qbase = blockIdx.y * 4096;

    cp128(s0 + PA_K,           g_Kh + m0 * HD, 128, tid);
    cp128(s0 + PA_K + PA_K_LO, g_Kl + m0 * HD, 128, tid);
    CP_COMMIT();
    cp128(s0 + PA_Q,           g_Qh + qbase * HD, 32, tid);
    cp128(s0 + PA_Q + PA_Q_LO, g_Ql + qbase * HD, 32, tid);
    CP_COMMIT();
    CP_WAIT1();
    __syncthreads();

    uint32_t Ah[8][4], Al[8][4];
    {
        uint32_t arow = (uint32_t)(wid * 16 + (lane & 7) + ((lane >> 3) & 1) * 8);
        uint32_t acol = (uint32_t)((lane >> 4) * 8);
        #pragma unroll
        for (int k = 0; k < 8; k++) {
            uint32_t a = s0 + PA_K + arow * ST128 + (k * 16 + acol) * 2;
            LDSM4(Ah[k], a);
            LDSM4(Al[k], a + PA_K_LO);
        }
    }

    const uint32_t r0 = (uint32_t)(wid * 16 + (lane >> 2));   // block-local key row
    float rs0 = 0.0f, rs1 = 0.0f;

    for (int ch = 0; ch < 128; ch++) {
        if (ch < 127) {
            uint32_t qb = s0 + PA_Q + (uint32_t)((ch + 1) & 1) * PA_QSTG;
            cp128(qb,           g_Qh + (qbase + (ch + 1) * 32) * HD, 32, tid);
            cp128(qb + PA_Q_LO, g_Ql + (qbase + (ch + 1) * 32) * HD, 32, tid);
            CP_COMMIT();
            CP_WAIT1();
        } else CP_WAIT0();
        __syncthreads();   // Q ready; E staging from prev chunk flushed

        const uint32_t qb = s0 + PA_Q + (uint32_t)(ch & 1) * PA_QSTG;
        #pragma unroll
        for (int ns = 0; ns < 4; ns++) {
            float c[4] = {0.f, 0.f, 0.f, 0.f};
            #pragma unroll
            for (int kk = 0; kk < 4; kk++) {
                uint32_t Bh[4], Bl[4];
                uint32_t ba = qb + (uint32_t)(ns * 8 + (lane & 7)) * ST128
                                 + (uint32_t)(kk * 32 + ((lane >> 3) & 3) * 8) * 2;
                LDSM4(Bh, ba);
                LDSM4(Bl, ba + PA_Q_LO);
                MMA(c, Ah[2*kk],   Bh[0], Bh[1]);
                MMA(c, Al[2*kk],   Bh[0], Bh[1]);
                MMA(c, Ah[2*kk],   Bl[0], Bl[1]);
                MMA(c, Ah[2*kk+1], Bh[2], Bh[3]);
                MMA(c, Al[2*kk+1], Bh[2], Bh[3]);
                MMA(c, Ah[2*kk+1], Bl[2], Bl[3]);
            }
            float e0 = __expf(c[0] - ESHIFT), e1 = __expf(c[1] - ESHIFT);
            float e2 = __expf(c[2] - ESHIFT), e3 = __expf(c[3] - ESHIFT);
            rs0 += e0 + e1;
            rs1 += e2 + e3;
            __nv_bfloat162 h01 = __floats2bfloat162_rn(e0, e1);
            __nv_bfloat162 h23 = __floats2bfloat162_rn(e2, e3);
            __nv_bfloat162 l01 = __floats2bfloat162_rn(e0 - __bfloat162float(h01.x),
                                                       e1 - __bfloat162float(h01.y));
            __nv_bfloat162 l23 = __floats2bfloat162_rn(e2 - __bfloat162float(h23.x),
                                                       e3 - __bfloat162float(h23.y));
            uint32_t eo = PA_E + r0 * ST32 + (uint32_t)(ns * 8 + (lane & 3) * 2) * 2;
            *(uint32_t*)(sm + eo)                      = *(uint32_t*)&h01;
            *(uint32_t*)(sm + eo + 8 * ST32)           = *(uint32_t*)&h23;
            *(uint32_t*)(sm + eo + PA_E_LO)            = *(uint32_t*)&l01;
            *(uint32_t*)(sm + eo + PA_E_LO + 8 * ST32) = *(uint32_t*)&l23;
        }
        __syncthreads();
        // staging -> gmem E^T, coalesced 32B per thread per plane
        {
            int kr = tid >> 1, half = tid & 1;
            const size_t gq = (size_t)(m0 + kr) * SEQ + (qbase + ch * 32 + half * 16);
            uint32_t so = PA_E + (uint32_t)kr * ST32 + (uint32_t)half * 32;
            uint4 v0 = *(const uint4*)(sm + so);
            uint4 v1 = *(const uint4*)(sm + so + 16);
            *(uint4*)((__nv_bfloat16*)g_Eh + gq)     = v0;
            *(uint4*)((__nv_bfloat16*)g_Eh + gq + 8) = v1;
            uint4 w0 = *(const uint4*)(sm + so + PA_E_LO);
            uint4 w1 = *(const uint4*)(sm + so + PA_E_LO + 16);
            *(uint4*)((__nv_bfloat16*)g_El + gq)     = w0;
            *(uint4*)((__nv_bfloat16*)g_El + gq + 8) = w1;
        }
    }

    // sum across the 4 lanes sharing each key row
    rs0 += __shfl_xor_sync(0xffffffffu, rs0, 1);
    rs0 += __shfl_xor_sync(0xffffffffu, rs0, 2);
    rs1 += __shfl_xor_sync(0xffffffffu, rs1, 1);
    rs1 += __shfl_xor_sync(0xffffffffu, rs1, 2);
    if ((lane & 3) == 0) {
        int r = m0 + wid * 16 + (lane >> 2);
        g_psum[blockIdx.y][r] = rs0;
        g_psum[blockIdx.y][r + 8] = rs1;
    }
}

// ============================ pass B ========================================
// grid(64,2): 128 queries x 4096 keys. Pure PV GEMM: A = E (from gmem, already
// split), B = V'^T. Per chunk = 64 keys. No epilogue math at all.
#define PB_E      0u        // per stage: hi [64][ST128], lo +17408; stride 34816
#define PB_E_LO   17408u
#define PB_ESTG   34816u
#define PB_V      69632u    // per stage: hi [128][ST64], lo +18432; stride 36864
#define PB_V_LO   18432u
#define PB_VSTG   36864u
#define PB_SMEM   143360

__global__ __launch_bounds__(256, 1)
void passB_kernel() {
    extern __shared__ char sm[];
    const uint32_t s0 = smem_u32(sm);
    const int tid = threadIdx.x, wid = tid >> 5, lane = tid & 31;
    const int q0 = blockIdx.x * 128, mbase = blockIdx.y * 4096;

    // prefetch chunk 0
    {
        uint32_t eb = s0 + PB_E, vb = s0 + PB_V;
        for (int i = tid; i < 1024; i += 256) {
            int r = i >> 4, c = i & 15;
            const size_t g = (size_t)(mbase + r) * SEQ + q0 + c * 8;
            CP16(eb + (uint32_t)r * ST128 + (uint32_t)c * 16, (__nv_bfloat16*)g_Eh + g);
            CP16(eb + PB_E_LO + (uint32_t)r * ST128 + (uint32_t)c * 16, (__nv_bfloat16*)g_El + g);
        }
        for (int i = tid; i < 1024; i += 256) {
            int r = i >> 3, c = i & 7;
            const size_t g = (size_t)r * SEQ + mbase + c * 8;
            CP16(vb + (uint32_t)r * ST64 + (uint32_t)c * 16, (__nv_bfloat16*)g_Vth + g);
            CP16(vb + PB_V_LO + (uint32_t)r * ST64 + (uint32_t)c * 16, (__nv_bfloat16*)g_Vtl + g);
        }
        CP_COMMIT();
    }

    float Co[16][4];
    #pragma unroll
    for (int i = 0; i < 16; i++)
        #pragma unroll
        for (int j = 0; j < 4; j++) Co[i][j] = 0.0f;

    // lane mapping for ldmatrix.trans A-frags from E^T [k][q] tiles
    const uint32_t krl = (uint32_t)((lane & 7) + ((lane >> 4) << 3));
    const uint32_t qo  = (uint32_t)(wid * 16 + ((lane >> 3) & 1) * 8);

    for (int ch = 0; ch < 64; ch++) {
        if (ch < 63) {
            const int mc = mbase + (ch + 1) * 64;
            uint32_t eb = s0 + PB_E + (uint32_t)((ch + 1) & 1) * PB_ESTG;
            uint32_t vb = s0 + PB_V + (uint32_t)((ch + 1) & 1) * PB_VSTG;
            for (int i = tid; i < 1024; i += 256) {
                int r = i >> 4, c = i & 15;
                const size_t g = (size_t)(mc + r) * SEQ + q0 + c * 8;
                CP16(eb + (uint32_t)r * ST128 + (uint32_t)c * 16, (__nv_bfloat16*)g_Eh + g);
                CP16(eb + PB_E_LO + (uint32_t)r * ST128 + (uint32_t)c * 16, (__nv_bfloat16*)g_El + g);
            }
            for (int i = tid; i < 1024; i += 256) {
                int r = i >> 3, c = i & 7;
                const size_t g = (size_t)r * SEQ + mc + c * 8;
                CP16(vb + (uint32_t)r * ST64 + (uint32_t)c * 16, (__nv_bfloat16*)g_Vth + g);
                CP16(vb + PB_V_LO + (uint32_t)r * ST64 + (uint32_t)c * 16, (__nv_bfloat16*)g_Vtl + g);
            }
            CP_COMMIT();
            CP_WAIT1();
        } else CP_WAIT0();
        __syncthreads();

        const uint32_t eb = s0 + PB_E + (uint32_t)(ch & 1) * PB_ESTG;
        const uint32_t vb = s0 + PB_V + (uint32_t)(ch & 1) * PB_VSTG;

        // A-frags: E[16q x 16k] per kk via ldmatrix.trans on E^T
        uint32_t AEh[4][4], AEl[4][4];
        #pragma unroll
        for (int kk = 0; kk < 4; kk++) {
            uint32_t a = eb + (uint32_t)(kk * 16 + krl) * ST128 + qo * 2;
            LDSM4T(AEh[kk], a);
            LDSM4T(AEl[kk], a + PB_E_LO);
        }

        #pragma unroll
        for (int ns = 0; ns < 16; ns++) {
            #pragma unroll
            for (int h = 0; h < 2; h++) {
                uint32_t Bh[4], Bl[4];
                uint32_t va = vb + (uint32_t)(ns * 8 + (lane & 7)) * ST64
                                 + (uint32_t)(h * 32 + (lane >> 3) * 8) * 2;
                LDSM4(Bh, va);
                LDSM4(Bl, va + PB_V_LO);
                MMA(Co[ns], AEh[2*h],   Bh[0], Bh[1]);
                MMA(Co[ns], AEl[2*h],   Bh[0], Bh[1]);
                MMA(Co[ns], AEh[2*h],   Bl[0], Bl[1]);
                MMA(Co[ns], AEh[2*h+1], Bh[2], Bh[3]);
                MMA(Co[ns], AEl[2*h+1], Bh[2], Bh[3]);
                MMA(Co[ns], AEh[2*h+1], Bl[2], Bl[3]);
            }
        }
        __syncthreads();
    }

    float* gp = g_part[blockIdx.y];
    int row0 = q0 + wid * 16 + (lane >> 2);
    #pragma unroll
    for (int ns = 0; ns < 16; ns++) {
        int col = ns * 8 + (lane & 3) * 2;
        *(float2*)(gp + (size_t)row0 * HD + col)       = make_float2(Co[ns][0], Co[ns][1]);
        *(float2*)(gp + (size_t)(row0 + 8) * HD + col) = make_float2(Co[ns][2], Co[ns][3]);
    }
}

__global__ void add_kernel(float* __restrict__ out) {
    int i = blockIdx.x * blockDim.x + threadIdx.x;
    float4 a = *(const float4*)(g_part[0] + (size_t)i * 4);
    float4 b = *(const float4*)(g_part[1] + (size_t)i * 4);
    *(float4*)(out + (size_t)i * 4) = make_float4(a.x + b.x, a.y + b.y, a.z + b.z, a.w + b.w);
}

// ---------------------------------------------------------------------------
extern "C" void kernel_launch(void* const* d_in, const int* in_sizes, int n_in,
                              void* d_out, int out_size) {
    (void)in_sizes; (void)n_in; (void)out_size;
    const float* Q = (const float*)d_in[0];
    const float* K = (const float*)d_in[1];
    const float* V = (const float*)d_in[2];
    float* out = (float*)d_out;

    cudaFuncSetAttribute(passA_kernel, cudaFuncAttributeMaxDynamicSharedMemorySize, PA_SMEM);
    cudaFuncSetAttribute(passB_kernel, cudaFuncAttributeMaxDynamicSharedMemorySize, PB_SMEM);

    conv_qk_kernel<<<SEQ * HD / 256, 256>>>(Q, K);
    passA_kernel<<<dim3(64, 2), 256, PA_SMEM>>>();
    scale_v_kernel<<<SEQ / 64, 128>>>(V);
    passB_kernel<<<dim3(64, 2), 256, PB_SMEM>>>();
    add_kernel<<<SEQ * HD / 1024, 256>>>(out);
}

// round 8
// speedup vs baseline: 1.6733x; 1.6733x over previous
#include <cuda_runtime.h>
#include <cuda_bf16.h>
#include <cstdint>

#define SEQ 8192
#define HD  128

__device__ __align__(256) __nv_bfloat16 g_Qh[SEQ * HD];
__device__ __align__(256) __nv_bfloat16 g_Ql[SEQ * HD];
__device__ __align__(256) __nv_bfloat16 g_Kh[SEQ * HD];
__device__ __align__(256) __nv_bfloat16 g_Kl[SEQ * HD];
__device__ __align__(256) __nv_bfloat16 g_Vth[HD * SEQ];   // V'^T hi: [d][m]
__device__ __align__(256) __nv_bfloat16 g_Vtl[HD * SEQ];   // V'^T lo
__device__ __align__(256) __nv_bfloat16 g_Eh[(size_t)SEQ * SEQ];  // E^T hi: [k][q]
__device__ __align__(256) __nv_bfloat16 g_El[(size_t)SEQ * SEQ];  // E^T lo
__device__ __align__(8) float g_psum[2][SEQ];
__device__ __align__(16) float g_part[2][SEQ * HD];

#define ESHIFT 60.0f

__device__ __forceinline__ uint32_t smem_u32(const void* p) {
    uint32_t a;
    asm("{ .reg .u64 t; cvta.to.shared.u64 t, %1; cvt.u32.u64 %0, t; }" : "=r"(a) : "l"(p));
    return a;
}
#define CP16(dst, src) asm volatile("cp.async.cg.shared.global [%0], [%1], 16;" :: "r"(dst), "l"(src))
#define CP_COMMIT()    asm volatile("cp.async.commit_group;" ::: "memory")
#define CP_WAIT0()     asm volatile("cp.async.wait_group 0;" ::: "memory")
#define CP_WAIT1()     asm volatile("cp.async.wait_group 1;" ::: "memory")

#define LDSM4(r, addr) \
    asm volatile("ldmatrix.sync.aligned.m8n8.x4.shared.b16 {%0,%1,%2,%3}, [%4];" \
        : "=r"((r)[0]), "=r"((r)[1]), "=r"((r)[2]), "=r"((r)[3]) : "r"(addr))
#define LDSM4T(r, addr) \
    asm volatile("ldmatrix.sync.aligned.m8n8.x4.trans.shared.b16 {%0,%1,%2,%3}, [%4];" \
        : "=r"((r)[0]), "=r"((r)[1]), "=r"((r)[2]), "=r"((r)[3]) : "r"(addr))

#define MMA(c, a, b0, b1) \
    asm volatile("mma.sync.aligned.m16n8k16.row.col.f32.bf16.bf16.f32 " \
        "{%0,%1,%2,%3},{%4,%5,%6,%7},{%8,%9},{%0,%1,%2,%3};" \
        : "+f"((c)[0]), "+f"((c)[1]), "+f"((c)[2]), "+f"((c)[3]) \
        : "r"((a)[0]), "r"((a)[1]), "r"((a)[2]), "r"((a)[3]), "r"(b0), "r"(b1))

#define ST128 272u   // 128-col bf16 rows (256B + 16 pad)
#define ST64  144u   // 64-col bf16 rows (128B + 16 pad)
#define ST32  80u    // 32-col bf16 rows (64B + 16 pad)

__device__ __forceinline__ void cp128(uint32_t dst, const __nv_bfloat16* g, int rows, int tid) {
    for (int i = tid; i < rows * 16; i += 256) {
        int r = i >> 4, c = i & 15;
        CP16(dst + (uint32_t)r * ST128 + (uint32_t)c * 16, g + r * HD + c * 8);
    }
}

// ============================ converts ======================================
__global__ void conv_qk_kernel(const float* __restrict__ Q, const float* __restrict__ K) {
    int i = blockIdx.x * blockDim.x + threadIdx.x;
    if (i >= SEQ * HD) return;
    float q = Q[i];
    __nv_bfloat16 qh = __float2bfloat16_rn(q);
    g_Qh[i] = qh; g_Ql[i] = __float2bfloat16_rn(q - __bfloat162float(qh));
    float k = K[i];
    __nv_bfloat16 kh = __float2bfloat16_rn(k);
    g_Kh[i] = kh; g_Kl[i] = __float2bfloat16_rn(k - __bfloat162float(kh));
}

// V'[m,:] = V[m,:] / colsumE[m], transposed + split hi/lo
__global__ void scale_v_kernel(const float* __restrict__ V) {
    __shared__ float sv[64 * HD];
    __shared__ float sinv[64];
    int m0 = blockIdx.x * 64;
    for (int i = threadIdx.x; i < 64 * HD; i += 128) sv[i] = V[m0 * HD + i];
    if (threadIdx.x < 64) {
        int m = m0 + threadIdx.x;
        sinv[threadIdx.x] = 1.0f / (g_psum[0][m] + g_psum[1][m]);
    }
    __syncthreads();
    for (int i = threadIdx.x; i < 64 * HD; i += 128) {
        int d = i >> 6, j = i & 63;
        float v = sv[j * HD + d] * sinv[j];
        __nv_bfloat16 h = __float2bfloat16_rn(v);
        g_Vth[d * SEQ + m0 + j] = h;
        g_Vtl[d * SEQ + m0 + j] = __float2bfloat16_rn(v - __bfloat162float(h));
    }
}

// ============================ pass A ========================================
// grid(128,2), 256 thr, 2 CTA/SM. Tile: 64 keys x 4096 queries, 32-q chunks.
// Warp(kw 0..3, qg 0..1): 16 keys x 16 q. E=exp(S-60) -> hi/lo -> staged(2buf)
// -> gmem E^T flush overlapped with next chunk's MMAs. Colsums via smem.
#define PA_K      0u
#define PA_K_LO   17408u                  // 64*272
#define PA_Q      34816u
#define PA_QSTG   17408u                  // stage stride (hi 8704 + lo 8704)
#define PA_Q_LO   8704u
#define PA_E      69632u                  // stage stride 10240 (hi 5120 + lo 5120)
#define PA_ESTG   10240u
#define PA_E_LO   5120u
#define PA_SMEM   90112

__global__ __launch_bounds__(256, 2)
void passA_kernel() {
    extern __shared__ char sm[];
    __shared__ float red[64][2];
    const uint32_t s0 = smem_u32(sm);
    const int tid = threadIdx.x, wid = tid >> 5, lane = tid & 31;
    const int kw = wid & 3, qg = wid >> 2;
    const int m0 = blockIdx.x * 64, qbase = blockIdx.y * 4096;

    cp128(s0 + PA_K,           g_Kh + m0 * HD, 64, tid);
    cp128(s0 + PA_K + PA_K_LO, g_Kl + m0 * HD, 64, tid);
    CP_COMMIT();
    cp128(s0 + PA_Q,           g_Qh + qbase * HD, 32, tid);
    cp128(s0 + PA_Q + PA_Q_LO, g_Ql + qbase * HD, 32, tid);
    CP_COMMIT();
    CP_WAIT1();
    __syncthreads();

    // persistent A (K) fragments: warp's 16 key rows
    uint32_t Ah[8][4], Al[8][4];
    {
        uint32_t arow = (uint32_t)(kw * 16 + (lane & 7) + ((lane >> 3) & 1) * 8);
        uint32_t acol = (uint32_t)((lane >> 4) * 8);
        #pragma unroll
        for (int k = 0; k < 8; k++) {
            uint32_t a = s0 + PA_K + arow * ST128 + (k * 16 + acol) * 2;
            LDSM4(Ah[k], a);
            LDSM4(Al[k], a + PA_K_LO);
        }
    }

    const uint32_t r0 = (uint32_t)(kw * 16 + (lane >> 2));
    float rs0 = 0.0f, rs1 = 0.0f;

    for (int ch = 0; ch < 128; ch++) {
        if (ch < 127) {
            uint32_t qb = s0 + PA_Q + (uint32_t)((ch + 1) & 1) * PA_QSTG;
            cp128(qb,           g_Qh + (qbase + (ch + 1) * 32) * HD, 32, tid);
            cp128(qb + PA_Q_LO, g_Ql + (qbase + (ch + 1) * 32) * HD, 32, tid);
            CP_COMMIT();
            CP_WAIT1();
        } else CP_WAIT0();
        __syncthreads();

        // flush previous chunk's staged E (overlaps with MMAs below)
        if (ch > 0) {
            const uint32_t es = PA_E + (uint32_t)((ch - 1) & 1) * PA_ESTG;
            int kr = tid >> 2, quarter = tid & 3;
            uint32_t so = es + (uint32_t)kr * ST32 + (uint32_t)quarter * 16;
            const size_t gq = (size_t)(m0 + kr) * SEQ + (qbase + (ch - 1) * 32 + quarter * 8);
            *(uint4*)((__nv_bfloat16*)g_Eh + gq) = *(const uint4*)(sm + so);
            *(uint4*)((__nv_bfloat16*)g_El + gq) = *(const uint4*)(sm + so + PA_E_LO);
        }

        const uint32_t qb = s0 + PA_Q + (uint32_t)(ch & 1) * PA_QSTG;
        const uint32_t es = PA_E + (uint32_t)(ch & 1) * PA_ESTG;
        #pragma unroll
        for (int ns = 0; ns < 2; ns++) {
            float cA[4] = {0.f, 0.f, 0.f, 0.f};
            float cB[4] = {0.f, 0.f, 0.f, 0.f};
            #pragma unroll
            for (int kk = 0; kk < 4; kk++) {
                uint32_t Bh[4], Bl[4];
                uint32_t ba = qb + (uint32_t)(qg * 16 + ns * 8 + (lane & 7)) * ST128
                                 + (uint32_t)(kk * 32 + ((lane >> 3) & 3) * 8) * 2;
                LDSM4(Bh, ba);
                LDSM4(Bl, ba + PA_Q_LO);
                MMA(cA, Ah[2*kk],   Bh[0], Bh[1]);
                MMA(cB, Al[2*kk],   Bh[0], Bh[1]);
                MMA(cA, Ah[2*kk],   Bl[0], Bl[1]);
                MMA(cA, Ah[2*kk+1], Bh[2], Bh[3]);
                MMA(cB, Al[2*kk+1], Bh[2], Bh[3]);
                MMA(cA, Ah[2*kk+1], Bl[2], Bl[3]);
            }
            float e0 = __expf(cA[0] + cB[0] - ESHIFT);
            float e1 = __expf(cA[1] + cB[1] - ESHIFT);
            float e2 = __expf(cA[2] + cB[2] - ESHIFT);
            float e3 = __expf(cA[3] + cB[3] - ESHIFT);
            rs0 += e0 + e1;
            rs1 += e2 + e3;
            __nv_bfloat162 h01 = __floats2bfloat162_rn(e0, e1);
            __nv_bfloat162 h23 = __floats2bfloat162_rn(e2, e3);
            __nv_bfloat162 l01 = __floats2bfloat162_rn(e0 - __bfloat162float(h01.x),
                                                       e1 - __bfloat162float(h01.y));
            __nv_bfloat162 l23 = __floats2bfloat162_rn(e2 - __bfloat162float(h23.x),
                                                       e3 - __bfloat162float(h23.y));
            uint32_t eo = es + r0 * ST32 + (uint32_t)(qg * 16 + ns * 8 + (lane & 3) * 2) * 2;
            *(uint32_t*)(sm + eo)                      = *(uint32_t*)&h01;
            *(uint32_t*)(sm + eo + 8 * ST32)           = *(uint32_t*)&h23;
            *(uint32_t*)(sm + eo + PA_E_LO)            = *(uint32_t*)&l01;
            *(uint32_t*)(sm + eo + PA_E_LO + 8 * ST32) = *(uint32_t*)&l23;
        }
        __syncthreads();
    }
    // final flush (chunk 127 staged in buffer 1)
    {
        const uint32_t es = PA_E + (uint32_t)(127 & 1) * PA_ESTG;
        int kr = tid >> 2, quarter = tid & 3;
        uint32_t so = es + (uint32_t)kr * ST32 + (uint32_t)quarter * 16;
        const size_t gq = (size_t)(m0 + kr) * SEQ + (qbase + 127 * 32 + quarter * 8);
        *(uint4*)((__nv_bfloat16*)g_Eh + gq) = *(const uint4*)(sm + so);
        *(uint4*)((__nv_bfloat16*)g_El + gq) = *(const uint4*)(sm + so + PA_E_LO);
    }

    // colsum reduction: lanes sharing a row, then the two qg warps
    rs0 += __shfl_xor_sync(0xffffffffu, rs0, 1);
    rs0 += __shfl_xor_sync(0xffffffffu, rs0, 2);
    rs1 += __shfl_xor_sync(0xffffffffu, rs1, 1);
    rs1 += __shfl_xor_sync(0xffffffffu, rs1, 2);
    if ((lane & 3) == 0) {
        red[kw * 16 + (lane >> 2)][qg] = rs0;
        red[kw * 16 + (lane >> 2) + 8][qg] = rs1;
    }
    __syncthreads();
    if (tid < 64) g_psum[blockIdx.y][m0 + tid] = red[tid][0] + red[tid][1];
}

// ============================ pass B ========================================
// grid(128,2), 256 thr, 2 CTA/SM. Tile: 64 q x 128 d, 64-key chunks.
// Warp(qw 0..3, dw 0..1): 16 q x 64 d. Pure PV GEMM, zero epilogue math.
#define PB_E      0u        // stage stride 18432 (hi 9216 + lo 9216)
#define PB_ESTG   18432u
#define PB_E_LO   9216u
#define PB_V      36864u    // stage stride 36864 (hi 18432 + lo 18432)
#define PB_VSTG   36864u
#define PB_V_LO   18432u
#define PB_SMEM   110592

__global__ __launch_bounds__(256, 2)
void passB_kernel() {
    extern __shared__ char sm[];
    const uint32_t s0 = smem_u32(sm);
    const int tid = threadIdx.x, wid = tid >> 5, lane = tid & 31;
    const int qw = wid & 3, dw = wid >> 2;
    const int q0 = blockIdx.x * 64, mbase = blockIdx.y * 4096;

    // prefetch chunk 0
    {
        uint32_t eb = s0 + PB_E, vb = s0 + PB_V;
        for (int i = tid; i < 512; i += 256) {
            int r = i >> 3, c = i & 7;
            const size_t g = (size_t)(mbase + r) * SEQ + q0 + c * 8;
            CP16(eb + (uint32_t)r * ST64 + (uint32_t)c * 16, (__nv_bfloat16*)g_Eh + g);
            CP16(eb + PB_E_LO + (uint32_t)r * ST64 + (uint32_t)c * 16, (__nv_bfloat16*)g_El + g);
        }
        for (int i = tid; i < 1024; i += 256) {
            int r = i >> 3, c = i & 7;
            const size_t g = (size_t)r * SEQ + mbase + c * 8;
            CP16(vb + (uint32_t)r * ST64 + (uint32_t)c * 16, (__nv_bfloat16*)g_Vth + g);
            CP16(vb + PB_V_LO + (uint32_t)r * ST64 + (uint32_t)c * 16, (__nv_bfloat16*)g_Vtl + g);
        }
        CP_COMMIT();
    }

    float Co[8][4];
    #pragma unroll
    for (int i = 0; i < 8; i++)
        #pragma unroll
        for (int j = 0; j < 4; j++) Co[i][j] = 0.0f;

    const uint32_t krl = (uint32_t)((lane & 7) + ((lane >> 4) << 3));
    const uint32_t qo  = (uint32_t)(qw * 16 + ((lane >> 3) & 1) * 8);

    for (int ch = 0; ch < 64; ch++) {
        if (ch < 63) {
            const int mc = mbase + (ch + 1) * 64;
            uint32_t eb = s0 + PB_E + (uint32_t)((ch + 1) & 1) * PB_ESTG;
            uint32_t vb = s0 + PB_V + (uint32_t)((ch + 1) & 1) * PB_VSTG;
            for (int i = tid; i < 512; i += 256) {
                int r = i >> 3, c = i & 7;
                const size_t g = (size_t)(mc + r) * SEQ + q0 + c * 8;
                CP16(eb + (uint32_t)r * ST64 + (uint32_t)c * 16, (__nv_bfloat16*)g_Eh + g);
                CP16(eb + PB_E_LO + (uint32_t)r * ST64 + (uint32_t)c * 16, (__nv_bfloat16*)g_El + g);
            }
            for (int i = tid; i < 1024; i += 256) {
                int r = i >> 3, c = i & 7;
                const size_t g = (size_t)r * SEQ + mc + c * 8;
                CP16(vb + (uint32_t)r * ST64 + (uint32_t)c * 16, (__nv_bfloat16*)g_Vth + g);
                CP16(vb + PB_V_LO + (uint32_t)r * ST64 + (uint32_t)c * 16, (__nv_bfloat16*)g_Vtl + g);
            }
            CP_COMMIT();
            CP_WAIT1();
        } else CP_WAIT0();
        __syncthreads();

        const uint32_t eb = s0 + PB_E + (uint32_t)(ch & 1) * PB_ESTG;
        const uint32_t vb = s0 + PB_V + (uint32_t)(ch & 1) * PB_VSTG;

        // A-frags: E[16q x 16k] per kk via ldmatrix.trans on E^T [k][q]
        uint32_t AEh[4][4], AEl[4][4];
        #pragma unroll
        for (int kk = 0; kk < 4; kk++) {
            uint32_t a = eb + (uint32_t)(kk * 16 + krl) * ST64 + qo * 2;
            LDSM4T(AEh[kk], a);
            LDSM4T(AEl[kk], a + PB_E_LO);
        }

        #pragma unroll
        for (int ns = 0; ns < 8; ns++) {
            #pragma unroll
            for (int h = 0; h < 2; h++) {
                uint32_t Bh[4], Bl[4];
                uint32_t va = vb + (uint32_t)(dw * 64 + ns * 8 + (lane & 7)) * ST64
                                 + (uint32_t)(h * 32 + (lane >> 3) * 8) * 2;
                LDSM4(Bh, va);
                LDSM4(Bl, va + PB_V_LO);
                MMA(Co[ns], AEh[2*h],   Bh[0], Bh[1]);
                MMA(Co[ns], AEl[2*h],   Bh[0], Bh[1]);
                MMA(Co[ns], AEh[2*h],   Bl[0], Bl[1]);
                MMA(Co[ns], AEh[2*h+1], Bh[2], Bh[3]);
                MMA(Co[ns], AEl[2*h+1], Bh[2], Bh[3]);
                MMA(Co[ns], AEh[2*h+1], Bl[2], Bl[3]);
            }
        }
        __syncthreads();
    }

    float* gp = g_part[blockIdx.y];
    int row0 = q0 + qw * 16 + (lane >> 2);
    #pragma unroll
    for (int ns = 0; ns < 8; ns++) {
        int col = dw * 64 + ns * 8 + (lane & 3) * 2;
        *(float2*)(gp + (size_t)row0 * HD + col)       = make_float2(Co[ns][0], Co[ns][1]);
        *(float2*)(gp + (size_t)(row0 + 8) * HD + col) = make_float2(Co[ns][2], Co[ns][3]);
    }
}

__global__ void add_kernel(float* __restrict__ out) {
    int i = blockIdx.x * blockDim.x + threadIdx.x;
    float4 a = *(const float4*)(g_part[0] + (size_t)i * 4);
    float4 b = *(const float4*)(g_part[1] + (size_t)i * 4);
    *(float4*)(out + (size_t)i * 4) = make_float4(a.x + b.x, a.y + b.y, a.z + b.z, a.w + b.w);
}

// ---------------------------------------------------------------------------
extern "C" void kernel_launch(void* const* d_in, const int* in_sizes, int n_in,
                              void* d_out, int out_size) {
    (void)in_sizes; (void)n_in; (void)out_size;
    const float* Q = (const float*)d_in[0];
    const float* K = (const float*)d_in[1];
    const float* V = (const float*)d_in[2];
    float* out = (float*)d_out;

    cudaFuncSetAttribute(passA_kernel, cudaFuncAttributeMaxDynamicSharedMemorySize, PA_SMEM);
    cudaFuncSetAttribute(passB_kernel, cudaFuncAttributeMaxDynamicSharedMemorySize, PB_SMEM);

    conv_qk_kernel<<<SEQ * HD / 256, 256>>>(Q, K);
    passA_kernel<<<dim3(128, 2), 256, PA_SMEM>>>();
    scale_v_kernel<<<SEQ / 64, 128>>>(V);
    passB_kernel<<<dim3(128, 2), 256, PB_SMEM>>>();
    add_kernel<<<SEQ * HD / 1024, 256>>>(out);
}

// round 10
// speedup vs baseline: 1.6893x; 1.0095x over previous
#include <cuda_runtime.h>
#include <cuda_bf16.h>
#include <cstdint>

#define SEQ 8192
#define HD  128

__device__ __align__(256) __nv_bfloat16 g_Qh[SEQ * HD];
__device__ __align__(256) __nv_bfloat16 g_Ql[SEQ * HD];
__device__ __align__(256) __nv_bfloat16 g_Kh[SEQ * HD];
__device__ __align__(256) __nv_bfloat16 g_Kl[SEQ * HD];
__device__ __align__(256) __nv_bfloat16 g_Vth[HD * SEQ];   // V'^T hi: [d][m]
__device__ __align__(256) __nv_bfloat16 g_Vtl[HD * SEQ];   // V'^T lo
__device__ __align__(256) __nv_bfloat16 g_Eh[(size_t)SEQ * SEQ];  // E^T hi: [k][q]
__device__ __align__(256) __nv_bfloat16 g_El[(size_t)SEQ * SEQ];  // E^T lo
__device__ __align__(8) float g_psum[2][SEQ];
__device__ __align__(16) float g_part[2][SEQ * HD];

#define ESHIFT 60.0f

__device__ __forceinline__ uint32_t smem_u32(const void* p) {
    uint32_t a;
    asm("{ .reg .u64 t; cvta.to.shared.u64 t, %1; cvt.u32.u64 %0, t; }" : "=r"(a) : "l"(p));
    return a;
}
#define CP16(dst, src) asm volatile("cp.async.cg.shared.global [%0], [%1], 16;" :: "r"(dst), "l"(src))
#define CP_COMMIT()    asm volatile("cp.async.commit_group;" ::: "memory")
#define CP_WAIT0()     asm volatile("cp.async.wait_group 0;" ::: "memory")

#define LDSM4(r, addr) \
    asm volatile("ldmatrix.sync.aligned.m8n8.x4.shared.b16 {%0,%1,%2,%3}, [%4];" \
        : "=r"((r)[0]), "=r"((r)[1]), "=r"((r)[2]), "=r"((r)[3]) : "r"(addr))
#define LDSM4T(r, addr) \
    asm volatile("ldmatrix.sync.aligned.m8n8.x4.trans.shared.b16 {%0,%1,%2,%3}, [%4];" \
        : "=r"((r)[0]), "=r"((r)[1]), "=r"((r)[2]), "=r"((r)[3]) : "r"(addr))

#define MMA(c, a, b0, b1) \
    asm volatile("mma.sync.aligned.m16n8k16.row.col.f32.bf16.bf16.f32 " \
        "{%0,%1,%2,%3},{%4,%5,%6,%7},{%8,%9},{%0,%1,%2,%3};" \
        : "+f"((c)[0]), "+f"((c)[1]), "+f"((c)[2]), "+f"((c)[3]) \
        : "r"((a)[0]), "r"((a)[1]), "r"((a)[2]), "r"((a)[3]), "r"(b0), "r"(b1))

#define ST128 272u   // 128-col bf16 rows (256B + 16 pad)
#define ST64  144u   // 64-col bf16 rows (128B + 16 pad)
#define ST32  80u    // 32-col bf16 rows (64B + 16 pad)

__device__ __forceinline__ void cp128(uint32_t dst, const __nv_bfloat16* g, int rows, int tid) {
    for (int i = tid; i < rows * 16; i += 256) {
        int r = i >> 4, c = i & 15;
        CP16(dst + (uint32_t)r * ST128 + (uint32_t)c * 16, g + r * HD + c * 8);
    }
}

// ============================ converts ======================================
__global__ void conv_qk_kernel(const float* __restrict__ Q, const float* __restrict__ K) {
    int i = blockIdx.x * blockDim.x + threadIdx.x;   // one float4 per thread
    float4 q4 = *(const float4*)(Q + i * 4);
    float4 k4 = *(const float4*)(K + i * 4);
    float q[4] = {q4.x, q4.y, q4.z, q4.w};
    float k[4] = {k4.x, k4.y, k4.z, k4.w};
    __nv_bfloat16 qh[4], ql[4], kh[4], kl[4];
    #pragma unroll
    for (int j = 0; j < 4; j++) {
        qh[j] = __float2bfloat16_rn(q[j]);
        ql[j] = __float2bfloat16_rn(q[j] - __bfloat162float(qh[j]));
        kh[j] = __float2bfloat16_rn(k[j]);
        kl[j] = __float2bfloat16_rn(k[j] - __bfloat162float(kh[j]));
    }
    *(uint2*)(g_Qh + i * 4) = *(uint2*)qh;
    *(uint2*)(g_Ql + i * 4) = *(uint2*)ql;
    *(uint2*)(g_Kh + i * 4) = *(uint2*)kh;
    *(uint2*)(g_Kl + i * 4) = *(uint2*)kl;
}

// V'[m,:] = V[m,:] / colsumE[m], transposed + split hi/lo
__global__ void scale_v_kernel(const float* __restrict__ V) {
    __shared__ float sv[64 * HD];
    __shared__ float sinv[64];
    int m0 = blockIdx.x * 64;
    for (int i = threadIdx.x; i < 64 * HD; i += 128) sv[i] = V[m0 * HD + i];
    if (threadIdx.x < 64) {
        int m = m0 + threadIdx.x;
        sinv[threadIdx.x] = 1.0f / (g_psum[0][m] + g_psum[1][m]);
    }
    __syncthreads();
    for (int i = threadIdx.x; i < 64 * HD; i += 128) {
        int d = i >> 6, j = i & 63;
        float v = sv[j * HD + d] * sinv[j];
        __nv_bfloat16 h = __float2bfloat16_rn(v);
        g_Vth[d * SEQ + m0 + j] = h;
        g_Vtl[d * SEQ + m0 + j] = __float2bfloat16_rn(v - __bfloat162float(h));
    }
}

// ============================ pass A ========================================
// grid(128,2), 256 thr, 2 CTA/SM. Tile: 64 keys x 4096 queries, 32-q chunks.
// ONE barrier per chunk: [WAIT0][bar][issue next cp][flush E(ch-1)][MMA+epi].
#define PA_K      0u
#define PA_K_LO   17408u                  // 64*272
#define PA_Q      34816u
#define PA_QSTG   17408u                  // stage stride (hi 8704 + lo 8704)
#define PA_Q_LO   8704u
#define PA_E      69632u                  // stage stride 10240 (hi 5120 + lo 5120)
#define PA_ESTG   10240u
#define PA_E_LO   5120u
#define PA_SMEM   90112

__global__ __launch_bounds__(256, 2)
void passA_kernel() {
    extern __shared__ char sm[];
    __shared__ float red[64][2];
    const uint32_t s0 = smem_u32(sm);
    const int tid = threadIdx.x, wid = tid >> 5, lane = tid & 31;
    const int kw = wid & 3, qg = wid >> 2;
    const int m0 = blockIdx.x * 64, qbase = blockIdx.y * 4096;

    cp128(s0 + PA_K,           g_Kh + m0 * HD, 64, tid);
    cp128(s0 + PA_K + PA_K_LO, g_Kl + m0 * HD, 64, tid);
    cp128(s0 + PA_Q,           g_Qh + qbase * HD, 32, tid);
    cp128(s0 + PA_Q + PA_Q_LO, g_Ql + qbase * HD, 32, tid);
    CP_COMMIT();
    CP_WAIT0();
    __syncthreads();

    // persistent A (K) fragments: warp's 16 key rows
    uint32_t Ah[8][4], Al[8][4];
    {
        uint32_t arow = (uint32_t)(kw * 16 + (lane & 7) + ((lane >> 3) & 1) * 8);
        uint32_t acol = (uint32_t)((lane >> 4) * 8);
        #pragma unroll
        for (int k = 0; k < 8; k++) {
            uint32_t a = s0 + PA_K + arow * ST128 + (k * 16 + acol) * 2;
            LDSM4(Ah[k], a);
            LDSM4(Al[k], a + PA_K_LO);
        }
    }

    const uint32_t r0 = (uint32_t)(kw * 16 + (lane >> 2));
    float rs0 = 0.0f, rs1 = 0.0f;

    for (int ch = 0; ch < 128; ch++) {
        if (ch > 0) { CP_WAIT0(); }
        __syncthreads();
        // issue next chunk's Q loads (overlaps the MMA phase below)
        if (ch < 127) {
            uint32_t qb = s0 + PA_Q + (uint32_t)((ch + 1) & 1) * PA_QSTG;
            cp128(qb,           g_Qh + (qbase + (ch + 1) * 32) * HD, 32, tid);
            cp128(qb + PA_Q_LO, g_Ql + (qbase + (ch + 1) * 32) * HD, 32, tid);
            CP_COMMIT();
        }
        // flush previous chunk's staged E (overlaps with MMAs below)
        if (ch > 0) {
            const uint32_t es = PA_E + (uint32_t)((ch - 1) & 1) * PA_ESTG;
            int kr = tid >> 2, quarter = tid & 3;
            uint32_t so = es + (uint32_t)kr * ST32 + (uint32_t)quarter * 16;
            const size_t gq = (size_t)(m0 + kr) * SEQ + (qbase + (ch - 1) * 32 + quarter * 8);
            *(uint4*)((__nv_bfloat16*)g_Eh + gq) = *(const uint4*)(sm + so);
            *(uint4*)((__nv_bfloat16*)g_El + gq) = *(const uint4*)(sm + so + PA_E_LO);
        }

        const uint32_t qb = s0 + PA_Q + (uint32_t)(ch & 1) * PA_QSTG;
        const uint32_t es = PA_E + (uint32_t)(ch & 1) * PA_ESTG;
        #pragma unroll
        for (int ns = 0; ns < 2; ns++) {
            float cA[4] = {0.f, 0.f, 0.f, 0.f};
            float cB[4] = {0.f, 0.f, 0.f, 0.f};
            #pragma unroll
            for (int kk = 0; kk < 4; kk++) {
                uint32_t Bh[4], Bl[4];
                uint32_t ba = qb + (uint32_t)(qg * 16 + ns * 8 + (lane & 7)) * ST128
                                 + (uint32_t)(kk * 32 + ((lane >> 3) & 3) * 8) * 2;
                LDSM4(Bh, ba);
                LDSM4(Bl, ba + PA_Q_LO);
                MMA(cA, Ah[2*kk],   Bh[0], Bh[1]);
                MMA(cB, Al[2*kk],   Bh[0], Bh[1]);
                MMA(cA, Ah[2*kk],   Bl[0], Bl[1]);
                MMA(cA, Ah[2*kk+1], Bh[2], Bh[3]);
                MMA(cB, Al[2*kk+1], Bh[2], Bh[3]);
                MMA(cA, Ah[2*kk+1], Bl[2], Bl[3]);
            }
            float e0 = __expf(cA[0] + cB[0] - ESHIFT);
            float e1 = __expf(cA[1] + cB[1] - ESHIFT);
            float e2 = __expf(cA[2] + cB[2] - ESHIFT);
            float e3 = __expf(cA[3] + cB[3] - ESHIFT);
            rs0 += e0 + e1;
            rs1 += e2 + e3;
            __nv_bfloat162 h01 = __floats2bfloat162_rn(e0, e1);
            __nv_bfloat162 h23 = __floats2bfloat162_rn(e2, e3);
            __nv_bfloat162 l01 = __floats2bfloat162_rn(e0 - __bfloat162float(h01.x),
                                                       e1 - __bfloat162float(h01.y));
            __nv_bfloat162 l23 = __floats2bfloat162_rn(e2 - __bfloat162float(h23.x),
                                                       e3 - __bfloat162float(h23.y));
            uint32_t eo = es + r0 * ST32 + (uint32_t)(qg * 16 + ns * 8 + (lane & 3) * 2) * 2;
            *(uint32_t*)(sm + eo)                      = *(uint32_t*)&h01;
            *(uint32_t*)(sm + eo + 8 * ST32)           = *(uint32_t*)&h23;
            *(uint32_t*)(sm + eo + PA_E_LO)            = *(uint32_t*)&l01;
            *(uint32_t*)(sm + eo + PA_E_LO + 8 * ST32) = *(uint32_t*)&l23;
        }
    }
    __syncthreads();
    // final flush (chunk 127 staged in buffer 1)
    {
        const uint32_t es = PA_E + (uint32_t)(127 & 1) * PA_ESTG;
        int kr = tid >> 2, quarter = tid & 3;
        uint32_t so = es + (uint32_t)kr * ST32 + (uint32_t)quarter * 16;
        const size_t gq = (size_t)(m0 + kr) * SEQ + (qbase + 127 * 32 + quarter * 8);
        *(uint4*)((__nv_bfloat16*)g_Eh + gq) = *(const uint4*)(sm + so);
        *(uint4*)((__nv_bfloat16*)g_El + gq) = *(const uint4*)(sm + so + PA_E_LO);
    }

    // colsum reduction: lanes sharing a row, then the two qg warps
    rs0 += __shfl_xor_sync(0xffffffffu, rs0, 1);
    rs0 += __shfl_xor_sync(0xffffffffu, rs0, 2);
    rs1 += __shfl_xor_sync(0xffffffffu, rs1, 1);
    rs1 += __shfl_xor_sync(0xffffffffu, rs1, 2);
    if ((lane & 3) == 0) {
        red[kw * 16 + (lane >> 2)][qg] = rs0;
        red[kw * 16 + (lane >> 2) + 8][qg] = rs1;
    }
    __syncthreads();
    if (tid < 64) g_psum[blockIdx.y][m0 + tid] = red[tid][0] + red[tid][1];
}

// ============================ pass B ========================================
// grid(128,2), 256 thr, 2 CTA/SM. Tile: 64 q x 128 d, 64-key chunks.
// ONE barrier per chunk: [WAIT0][bar][issue next cp][LDSM A][MMA].
#define PB_E      0u        // stage stride 18432 (hi 9216 + lo 9216)
#define PB_ESTG   18432u
#define PB_E_LO   9216u
#define PB_V      36864u    // stage stride 36864 (hi 18432 + lo 18432)
#define PB_VSTG   36864u
#define PB_V_LO   18432u
#define PB_SMEM   110592

__device__ __forceinline__ void pb_issue(uint32_t s0, int mc, int q0, int stage, int tid) {
    uint32_t eb = s0 + PB_E + (uint32_t)stage * PB_ESTG;
    uint32_t vb = s0 + PB_V + (uint32_t)stage * PB_VSTG;
    for (int i = tid; i < 512; i += 256) {
        int r = i >> 3, c = i & 7;
        const size_t g = (size_t)(mc + r) * SEQ + q0 + c * 8;
        CP16(eb + (uint32_t)r * ST64 + (uint32_t)c * 16, (__nv_bfloat16*)g_Eh + g);
        CP16(eb + PB_E_LO + (uint32_t)r * ST64 + (uint32_t)c * 16, (__nv_bfloat16*)g_El + g);
    }
    for (int i = tid; i < 1024; i += 256) {
        int r = i >> 3, c = i & 7;
        const size_t g = (size_t)r * SEQ + mc + c * 8;
        CP16(vb + (uint32_t)r * ST64 + (uint32_t)c * 16, (__nv_bfloat16*)g_Vth + g);
        CP16(vb + PB_V_LO + (uint32_t)r * ST64 + (uint32_t)c * 16, (__nv_bfloat16*)g_Vtl + g);
    }
    CP_COMMIT();
}

__global__ __launch_bounds__(256, 2)
void passB_kernel() {
    extern __shared__ char sm[];
    const uint32_t s0 = smem_u32(sm);
    const int tid = threadIdx.x, wid = tid >> 5, lane = tid & 31;
    const int qw = wid & 3, dw = wid >> 2;
    const int q0 = blockIdx.x * 64, mbase = blockIdx.y * 4096;

    pb_issue(s0, mbase, q0, 0, tid);   // prefetch chunk 0

    float Co[8][4];
    #pragma unroll
    for (int i = 0; i < 8; i++)
        #pragma unroll
        for (int j = 0; j < 4; j++) Co[i][j] = 0.0f;

    const uint32_t krl = (uint32_t)((lane & 7) + ((lane >> 4) << 3));
    const uint32_t qo  = (uint32_t)(qw * 16 + ((lane >> 3) & 1) * 8);

    for (int ch = 0; ch < 64; ch++) {
        CP_WAIT0();
        __syncthreads();
        if (ch < 63) pb_issue(s0, mbase + (ch + 1) * 64, q0, (ch + 1) & 1, tid);

        const uint32_t eb = s0 + PB_E + (uint32_t)(ch & 1) * PB_ESTG;
        const uint32_t vb = s0 + PB_V + (uint32_t)(ch & 1) * PB_VSTG;

        // A-frags: E[16q x 16k] per kk via ldmatrix.trans on E^T [k][q]
        uint32_t AEh[4][4], AEl[4][4];
        #pragma unroll
        for (int kk = 0; kk < 4; kk++) {
            uint32_t a = eb + (uint32_t)(kk * 16 + krl) * ST64 + qo * 2;
            LDSM4T(AEh[kk], a);
            LDSM4T(AEl[kk], a + PB_E_LO);
        }

        #pragma unroll
        for (int ns = 0; ns < 8; ns++) {
            #pragma unroll
            for (int h = 0; h < 2; h++) {
                uint32_t Bh[4], Bl[4];
                uint32_t va = vb + (uint32_t)(dw * 64 + ns * 8 + (lane & 7)) * ST64
                                 + (uint32_t)(h * 32 + (lane >> 3) * 8) * 2;
                LDSM4(Bh, va);
                LDSM4(Bl, va + PB_V_LO);
                MMA(Co[ns], AEh[2*h],   Bh[0], Bh[1]);
                MMA(Co[ns], AEl[2*h],   Bh[0], Bh[1]);
                MMA(Co[ns], AEh[2*h],   Bl[0], Bl[1]);
                MMA(Co[ns], AEh[2*h+1], Bh[2], Bh[3]);
                MMA(Co[ns], AEl[2*h+1], Bh[2], Bh[3]);
                MMA(Co[ns], AEh[2*h+1], Bl[2], Bl[3]);
            }
        }
    }

    float* gp = g_part[blockIdx.y];
    int row0 = q0 + qw * 16 + (lane >> 2);
    #pragma unroll
    for (int ns = 0; ns < 8; ns++) {
        int col = dw * 64 + ns * 8 + (lane & 3) * 2;
        *(float2*)(gp + (size_t)row0 * HD + col)       = make_float2(Co[ns][0], Co[ns][1]);
        *(float2*)(gp + (size_t)(row0 + 8) * HD + col) = make_float2(Co[ns][2], Co[ns][3]);
    }
}

__global__ void add_kernel(float* __restrict__ out) {
    int i = blockIdx.x * blockDim.x + threadIdx.x;
    float4 a = *(const float4*)(g_part[0] + (size_t)i * 4);
    float4 b = *(const float4*)(g_part[1] + (size_t)i * 4);
    *(float4*)(out + (size_t)i * 4) = make_float4(a.x + b.x, a.y + b.y, a.z + b.z, a.w + b.w);
}

// ---------------------------------------------------------------------------
extern "C" void kernel_launch(void* const* d_in, const int* in_sizes, int n_in,
                              void* d_out, int out_size) {
    (void)in_sizes; (void)n_in; (void)out_size;
    const float* Q = (const float*)d_in[0];
    const float* K = (const float*)d_in[1];
    const float* V = (const float*)d_in[2];
    float* out = (float*)d_out;

    cudaFuncSetAttribute(passA_kernel, cudaFuncAttributeMaxDynamicSharedMemorySize, PA_SMEM);
    cudaFuncSetAttribute(passB_kernel, cudaFuncAttributeMaxDynamicSharedMemorySize, PB_SMEM);

    conv_qk_kernel<<<SEQ * HD / 1024, 256>>>(Q, K);
    passA_kernel<<<dim3(128, 2), 256, PA_SMEM>>>();
    scale_v_kernel<<<SEQ / 64, 128>>>(V);
    passB_kernel<<<dim3(128, 2), 256, PB_SMEM>>>();
    add_kernel<<<SEQ * HD / 1024, 256>>>(out);
}

// round 13
// speedup vs baseline: 1.7457x; 1.0334x over previous
#include <cuda_runtime.h>
#include <cuda_bf16.h>
#include <cstdint>

#define SEQ 8192
#define HD  128

__device__ __align__(256) __nv_bfloat16 g_Qh[SEQ * HD];
__device__ __align__(256) __nv_bfloat16 g_Ql[SEQ * HD];
__device__ __align__(256) __nv_bfloat16 g_Kh[SEQ * HD];
__device__ __align__(256) __nv_bfloat16 g_Kl[SEQ * HD];
__device__ __align__(256) __nv_bfloat16 g_Vth[HD * SEQ];   // V'^T hi: [d][m]
__device__ __align__(256) __nv_bfloat16 g_Vtl[HD * SEQ];   // V'^T lo
__device__ __align__(256) __nv_bfloat16 g_Eh[(size_t)SEQ * SEQ];  // E^T hi: [k][q]
__device__ __align__(256) __nv_bfloat16 g_El[(size_t)SEQ * SEQ];  // E^T lo
__device__ __align__(8) float g_psum[2][SEQ];
__device__ __align__(16) float g_part[2][SEQ * HD];

#define ESHIFT 60.0f

__device__ __forceinline__ uint32_t smem_u32(const void* p) {
    uint32_t a;
    asm("{ .reg .u64 t; cvta.to.shared.u64 t, %1; cvt.u32.u64 %0, t; }" : "=r"(a) : "l"(p));
    return a;
}
#define CP16(dst, src) asm volatile("cp.async.cg.shared.global [%0], [%1], 16;" :: "r"(dst), "l"(src))
#define CP_COMMIT()    asm volatile("cp.async.commit_group;" ::: "memory")
#define CP_WAIT0()     asm volatile("cp.async.wait_group 0;" ::: "memory")

#define LDSM4(r, addr) \
    asm volatile("ldmatrix.sync.aligned.m8n8.x4.shared.b16 {%0,%1,%2,%3}, [%4];" \
        : "=r"((r)[0]), "=r"((r)[1]), "=r"((r)[2]), "=r"((r)[3]) : "r"(addr))
#define LDSM4T(r, addr) \
    asm volatile("ldmatrix.sync.aligned.m8n8.x4.trans.shared.b16 {%0,%1,%2,%3}, [%4];" \
        : "=r"((r)[0]), "=r"((r)[1]), "=r"((r)[2]), "=r"((r)[3]) : "r"(addr))

#define MMA(c, a, b0, b1) \
    asm volatile("mma.sync.aligned.m16n8k16.row.col.f32.bf16.bf16.f32 " \
        "{%0,%1,%2,%3},{%4,%5,%6,%7},{%8,%9},{%0,%1,%2,%3};" \
        : "+f"((c)[0]), "+f"((c)[1]), "+f"((c)[2]), "+f"((c)[3]) \
        : "r"((a)[0]), "r"((a)[1]), "r"((a)[2]), "r"((a)[3]), "r"(b0), "r"(b1))

#define ST128 272u   // 128-col bf16 rows (256B + 16 pad)
#define ST64  144u   // 64-col bf16 rows (128B + 16 pad)
#define ST32  80u    // 32-col bf16 rows (64B + 16 pad)

__device__ __forceinline__ void cp128(uint32_t dst, const __nv_bfloat16* g, int rows, int tid) {
    for (int i = tid; i < rows * 16; i += 256) {
        int r = i >> 4, c = i & 15;
        CP16(dst + (uint32_t)r * ST128 + (uint32_t)c * 16, g + r * HD + c * 8);
    }
}

// ============================ converts ======================================
__global__ void conv_qk_kernel(const float* __restrict__ Q, const float* __restrict__ K) {
    int i = blockIdx.x * blockDim.x + threadIdx.x;   // one float4 per thread
    float4 q4 = *(const float4*)(Q + i * 4);
    float4 k4 = *(const float4*)(K + i * 4);
    float q[4] = {q4.x, q4.y, q4.z, q4.w};
    float k[4] = {k4.x, k4.y, k4.z, k4.w};
    __nv_bfloat16 qh[4], ql[4], kh[4], kl[4];
    #pragma unroll
    for (int j = 0; j < 4; j++) {
        qh[j] = __float2bfloat16_rn(q[j]);
        ql[j] = __float2bfloat16_rn(q[j] - __bfloat162float(qh[j]));
        kh[j] = __float2bfloat16_rn(k[j]);
        kl[j] = __float2bfloat16_rn(k[j] - __bfloat162float(kh[j]));
    }
    *(uint2*)(g_Qh + i * 4) = *(uint2*)qh;
    *(uint2*)(g_Ql + i * 4) = *(uint2*)ql;
    *(uint2*)(g_Kh + i * 4) = *(uint2*)kh;
    *(uint2*)(g_Kl + i * 4) = *(uint2*)kl;
}

// V'[m,:] = V[m,:] / colsumE[m], transposed + split hi/lo
__global__ void scale_v_kernel(const float* __restrict__ V) {
    __shared__ float sv[64 * HD];
    __shared__ float sinv[64];
    int m0 = blockIdx.x * 64;
    for (int i = threadIdx.x; i < 64 * HD; i += 128) sv[i] = V[m0 * HD + i];
    if (threadIdx.x < 64) {
        int m = m0 + threadIdx.x;
        sinv[threadIdx.x] = 1.0f / (g_psum[0][m] + g_psum[1][m]);
    }
    __syncthreads();
    for (int i = threadIdx.x; i < 64 * HD; i += 128) {
        int d = i >> 6, j = i & 63;
        float v = sv[j * HD + d] * sinv[j];
        __nv_bfloat16 h = __float2bfloat16_rn(v);
        g_Vth[d * SEQ + m0 + j] = h;
        g_Vtl[d * SEQ + m0 + j] = __float2bfloat16_rn(v - __bfloat162float(h));
    }
}

// ============================ pass A ========================================
// grid(128,2), 256 thr, 2 CTA/SM. Tile: 64 keys x 4096 queries, 32-q chunks.
// ONE barrier per chunk: [WAIT0][bar][issue next cp][flush E(ch-1)][MMA+epi].
#define PA_K      0u
#define PA_K_LO   17408u                  // 64*272
#define PA_Q      34816u
#define PA_QSTG   17408u                  // stage stride (hi 8704 + lo 8704)
#define PA_Q_LO   8704u
#define PA_E      69632u                  // stage stride 10240 (hi 5120 + lo 5120)
#define PA_ESTG   10240u
#define PA_E_LO   5120u
#define PA_SMEM   90112

__global__ __launch_bounds__(256, 2)
void passA_kernel() {
    extern __shared__ char sm[];
    __shared__ float red[64][2];
    const uint32_t s0 = smem_u32(sm);
    const int tid = threadIdx.x, wid = tid >> 5, lane = tid & 31;
    const int kw = wid & 3, qg = wid >> 2;
    const int m0 = blockIdx.x * 64, qbase = blockIdx.y * 4096;

    cp128(s0 + PA_K,           g_Kh + m0 * HD, 64, tid);
    cp128(s0 + PA_K + PA_K_LO, g_Kl + m0 * HD, 64, tid);
    cp128(s0 + PA_Q,           g_Qh + qbase * HD, 32, tid);
    cp128(s0 + PA_Q + PA_Q_LO, g_Ql + qbase * HD, 32, tid);
    CP_COMMIT();
    CP_WAIT0();
    __syncthreads();

    // persistent A (K) fragments: warp's 16 key rows
    uint32_t Ah[8][4], Al[8][4];
    {
        uint32_t arow = (uint32_t)(kw * 16 + (lane & 7) + ((lane >> 3) & 1) * 8);
        uint32_t acol = (uint32_t)((lane >> 4) * 8);
        #pragma unroll
        for (int k = 0; k < 8; k++) {
            uint32_t a = s0 + PA_K + arow * ST128 + (k * 16 + acol) * 2;
            LDSM4(Ah[k], a);
            LDSM4(Al[k], a + PA_K_LO);
        }
    }

    const uint32_t r0 = (uint32_t)(kw * 16 + (lane >> 2));
    float rs0 = 0.0f, rs1 = 0.0f;

    for (int ch = 0; ch < 128; ch++) {
        if (ch > 0) { CP_WAIT0(); }
        __syncthreads();
        if (ch < 127) {
            uint32_t qb = s0 + PA_Q + (uint32_t)((ch + 1) & 1) * PA_QSTG;
            cp128(qb,           g_Qh + (qbase + (ch + 1) * 32) * HD, 32, tid);
            cp128(qb + PA_Q_LO, g_Ql + (qbase + (ch + 1) * 32) * HD, 32, tid);
            CP_COMMIT();
        }
        // flush previous chunk's staged E (overlaps with MMAs below)
        if (ch > 0) {
            const uint32_t es = PA_E + (uint32_t)((ch - 1) & 1) * PA_ESTG;
            int kr = tid >> 2, quarter = tid & 3;
            uint32_t so = es + (uint32_t)kr * ST32 + (uint32_t)quarter * 16;
            const size_t gq = (size_t)(m0 + kr) * SEQ + (qbase + (ch - 1) * 32 + quarter * 8);
            *(uint4*)((__nv_bfloat16*)g_Eh + gq) = *(const uint4*)(sm + so);
            *(uint4*)((__nv_bfloat16*)g_El + gq) = *(const uint4*)(sm + so + PA_E_LO);
        }

        const uint32_t qb = s0 + PA_Q + (uint32_t)(ch & 1) * PA_QSTG;
        const uint32_t es = PA_E + (uint32_t)(ch & 1) * PA_ESTG;
        #pragma unroll
        for (int ns = 0; ns < 2; ns++) {
            float cA[4] = {0.f, 0.f, 0.f, 0.f};
            float cB[4] = {0.f, 0.f, 0.f, 0.f};
            #pragma unroll
            for (int kk = 0; kk < 4; kk++) {
                uint32_t Bh[4], Bl[4];
                uint32_t ba = qb + (uint32_t)(qg * 16 + ns * 8 + (lane & 7)) * ST128
                                 + (uint32_t)(kk * 32 + ((lane >> 3) & 3) * 8) * 2;
                LDSM4(Bh, ba);
                LDSM4(Bl, ba + PA_Q_LO);
                MMA(cA, Ah[2*kk],   Bh[0], Bh[1]);
                MMA(cB, Al[2*kk],   Bh[0], Bh[1]);
                MMA(cA, Ah[2*kk],   Bl[0], Bl[1]);
                MMA(cA, Ah[2*kk+1], Bh[2], Bh[3]);
                MMA(cB, Al[2*kk+1], Bh[2], Bh[3]);
                MMA(cA, Ah[2*kk+1], Bl[2], Bl[3]);
            }
            float e0 = __expf(cA[0] + cB[0] - ESHIFT);
            float e1 = __expf(cA[1] + cB[1] - ESHIFT);
            float e2 = __expf(cA[2] + cB[2] - ESHIFT);
            float e3 = __expf(cA[3] + cB[3] - ESHIFT);
            rs0 += e0 + e1;
            rs1 += e2 + e3;
            __nv_bfloat162 h01 = __floats2bfloat162_rn(e0, e1);
            __nv_bfloat162 h23 = __floats2bfloat162_rn(e2, e3);
            __nv_bfloat162 l01 = __floats2bfloat162_rn(e0 - __bfloat162float(h01.x),
                                                       e1 - __bfloat162float(h01.y));
            __nv_bfloat162 l23 = __floats2bfloat162_rn(e2 - __bfloat162float(h23.x),
                                                       e3 - __bfloat162float(h23.y));
            uint32_t eo = es + r0 * ST32 + (uint32_t)(qg * 16 + ns * 8 + (lane & 3) * 2) * 2;
            *(uint32_t*)(sm + eo)                      = *(uint32_t*)&h01;
            *(uint32_t*)(sm + eo + 8 * ST32)           = *(uint32_t*)&h23;
            *(uint32_t*)(sm + eo + PA_E_LO)            = *(uint32_t*)&l01;
            *(uint32_t*)(sm + eo + PA_E_LO + 8 * ST32) = *(uint32_t*)&l23;
        }
    }
    __syncthreads();
    // final flush (chunk 127 staged in buffer 1)
    {
        const uint32_t es = PA_E + (uint32_t)(127 & 1) * PA_ESTG;
        int kr = tid >> 2, quarter = tid & 3;
        uint32_t so = es + (uint32_t)kr * ST32 + (uint32_t)quarter * 16;
        const size_t gq = (size_t)(m0 + kr) * SEQ + (qbase + 127 * 32 + quarter * 8);
        *(uint4*)((__nv_bfloat16*)g_Eh + gq) = *(const uint4*)(sm + so);
        *(uint4*)((__nv_bfloat16*)g_El + gq) = *(const uint4*)(sm + so + PA_E_LO);
    }

    rs0 += __shfl_xor_sync(0xffffffffu, rs0, 1);
    rs0 += __shfl_xor_sync(0xffffffffu, rs0, 2);
    rs1 += __shfl_xor_sync(0xffffffffu, rs1, 1);
    rs1 += __shfl_xor_sync(0xffffffffu, rs1, 2);
    if ((lane & 3) == 0) {
        red[kw * 16 + (lane >> 2)][qg] = rs0;
        red[kw * 16 + (lane >> 2) + 8][qg] = rs1;
    }
    __syncthreads();
    if (tid < 64) g_psum[blockIdx.y][m0 + tid] = red[tid][0] + red[tid][1];
}

// ============================ pass B ========================================
// grid(64,2), 256 thr, 1 CTA/SM. CTA tile: 128 q x 128 d, 64-key chunks.
// Warp tile: 32 q x 64 d (2 q-subtiles sharing B fragments in registers).
#define PB_E      0u        // stage: hi [64][ST128] 17408 + lo 17408 = 34816
#define PB_ESTG   34816u
#define PB_E_LO   17408u
#define PB_V      69632u    // stage: hi [128][ST64] 18432 + lo 18432 = 36864
#define PB_VSTG   36864u
#define PB_V_LO   18432u
#define PB_SMEM   143360

__device__ __forceinline__ void pb_issue(uint32_t s0, int mc, int q0, int stage, int tid) {
    uint32_t eb = s0 + PB_E + (uint32_t)stage * PB_ESTG;
    uint32_t vb = s0 + PB_V + (uint32_t)stage * PB_VSTG;
    for (int i = tid; i < 1024; i += 256) {        // E: 64 rows x 128 q cols
        int r = i >> 4, c = i & 15;
        const size_t g = (size_t)(mc + r) * SEQ + q0 + c * 8;
        CP16(eb + (uint32_t)r * ST128 + (uint32_t)c * 16, (__nv_bfloat16*)g_Eh + g);
        CP16(eb + PB_E_LO + (uint32_t)r * ST128 + (uint32_t)c * 16, (__nv_bfloat16*)g_El + g);
    }
    for (int i = tid; i < 1024; i += 256) {        // V: 128 d rows x 64 k cols
        int r = i >> 3, c = i & 7;
        const size_t g = (size_t)r * SEQ + mc + c * 8;
        CP16(vb + (uint32_t)r * ST64 + (uint32_t)c * 16, (__nv_bfloat16*)g_Vth + g);
        CP16(vb + PB_V_LO + (uint32_t)r * ST64 + (uint32_t)c * 16, (__nv_bfloat16*)g_Vtl + g);
    }
    CP_COMMIT();
}

__global__ __launch_bounds__(256)
void passB_kernel() {
    extern __shared__ char sm[];
    const uint32_t s0 = smem_u32(sm);
    const int tid = threadIdx.x, wid = tid >> 5, lane = tid & 31;
    const int qw = wid & 3, dw = wid >> 2;
    const int q0 = blockIdx.x * 128, mbase = blockIdx.y * 4096;

    pb_issue(s0, mbase, q0, 0, tid);   // prefetch chunk 0

    float Co[2][8][4];
    #pragma unroll
    for (int qs = 0; qs < 2; qs++)
        #pragma unroll
        for (int i = 0; i < 8; i++)
            #pragma unroll
            for (int j = 0; j < 4; j++) Co[qs][i][j] = 0.0f;

    const uint32_t krl = (uint32_t)((lane & 7) + ((lane >> 4) << 3));

    for (int ch = 0; ch < 64; ch++) {
        CP_WAIT0();
        __syncthreads();
        if (ch < 63) pb_issue(s0, mbase + (ch + 1) * 64, q0, (ch + 1) & 1, tid);

        const uint32_t eb = s0 + PB_E + (uint32_t)(ch & 1) * PB_ESTG;
        const uint32_t vb = s0 + PB_V + (uint32_t)(ch & 1) * PB_VSTG;

        // A-frags for both q-subtiles: E[16q x 16k] per kk via ldmatrix.trans
        uint32_t AEh[2][4][4], AEl[2][4][4];
        #pragma unroll
        for (int qs = 0; qs < 2; qs++) {
            uint32_t qo = (uint32_t)(qw * 32 + qs * 16 + ((lane >> 3) & 1) * 8);
            #pragma unroll
            for (int kk = 0; kk < 4; kk++) {
                uint32_t a = eb + (uint32_t)(kk * 16 + krl) * ST128 + qo * 2;
                LDSM4T(AEh[qs][kk], a);
                LDSM4T(AEl[qs][kk], a + PB_E_LO);
            }
        }

        #pragma unroll
        for (int ns = 0; ns < 8; ns++) {
            #pragma unroll
            for (int h = 0; h < 2; h++) {
                uint32_t Bh[4], Bl[4];
                uint32_t va = vb + (uint32_t)(dw * 64 + ns * 8 + (lane & 7)) * ST64
                                 + (uint32_t)(h * 32 + (lane >> 3) * 8) * 2;
                LDSM4(Bh, va);
                LDSM4(Bl, va + PB_V_LO);
                #pragma unroll
                for (int qs = 0; qs < 2; qs++) {
                    MMA(Co[qs][ns], AEh[qs][2*h],   Bh[0], Bh[1]);
                    MMA(Co[qs][ns], AEl[qs][2*h],   Bh[0], Bh[1]);
                    MMA(Co[qs][ns], AEh[qs][2*h],   Bl[0], Bl[1]);
                    MMA(Co[qs][ns], AEh[qs][2*h+1], Bh[2], Bh[3]);
                    MMA(Co[qs][ns], AEl[qs][2*h+1], Bh[2], Bh[3]);
                    MMA(Co[qs][ns], AEh[qs][2*h+1], Bl[2], Bl[3]);
                }
            }
        }
    }

    float* gp = g_part[blockIdx.y];
    #pragma unroll
    for (int qs = 0; qs < 2; qs++) {
        int row0 = q0 + qw * 32 + qs * 16 + (lane >> 2);
        #pragma unroll
        for (int ns = 0; ns < 8; ns++) {
            int col = dw * 64 + ns * 8 + (lane & 3) * 2;
            *(float2*)(gp + (size_t)row0 * HD + col)       = make_float2(Co[qs][ns][0], Co[qs][ns][1]);
            *(float2*)(gp + (size_t)(row0 + 8) * HD + col) = make_float2(Co[qs][ns][2], Co[qs][ns][3]);
        }
    }
}

__global__ void add_kernel(float* __restrict__ out) {
    int i = blockIdx.x * blockDim.x + threadIdx.x;
    float4 a = *(const float4*)(g_part[0] + (size_t)i * 4);
    float4 b = *(const float4*)(g_part[1] + (size_t)i * 4);
    *(float4*)(out + (size_t)i * 4) = make_float4(a.x + b.x, a.y + b.y, a.z + b.z, a.w + b.w);
}

// ---------------------------------------------------------------------------
extern "C" void kernel_launch(void* const* d_in, const int* in_sizes, int n_in,
                              void* d_out, int out_size) {
    (void)in_sizes; (void)n_in; (void)out_size;
    const float* Q = (const float*)d_in[0];
    const float* K = (const float*)d_in[1];
    const float* V = (const float*)d_in[2];
    float* out = (float*)d_out;

    cudaFuncSetAttribute(passA_kernel, cudaFuncAttributeMaxDynamicSharedMemorySize, PA_SMEM);
    cudaFuncSetAttribute(passB_kernel, cudaFuncAttributeMaxDynamicSharedMemorySize, PB_SMEM);

    conv_qk_kernel<<<SEQ * HD / 1024, 256>>>(Q, K);
    passA_kernel<<<dim3(128, 2), 256, PA_SMEM>>>();
    scale_v_kernel<<<SEQ / 64, 128>>>(V);
    passB_kernel<<<dim3(64, 2), 256, PB_SMEM>>>();
    add_kernel<<<SEQ * HD / 1024, 256>>>(out);
}